// round 4
// baseline (speedup 1.0000x reference)
#include <cuda_runtime.h>
#include <cuda_fp16.h>
#include <math.h>
#include <stdint.h>

#define Bc 4
#define Tc 256
#define Uc 128
#define Ec 512
#define Dc 640
#define Hc 512
#define Vc 640

// Scratch (no cudaMalloc allowed).
__device__ float  g_enc[Bc * Tc * Hc];   // [B*T, H]
__device__ float  g_dec[Bc * Uc * Hc];   // [B*U, H]
__device__ __half g_Wt[Vc * Hc];         // W_out^T fp16: [V, H]

// ---------------------------------------------------------------------------
// Helpers (sm_80-era PTX only — no 'a'-gated instructions)
// ---------------------------------------------------------------------------
__device__ __forceinline__ uint32_t smem_u32(const void* p) {
    return (uint32_t)__cvta_generic_to_shared(p);
}
__device__ __forceinline__ void cp16(uint32_t dst, const void* src) {
    asm volatile("cp.async.cg.shared.global [%0], [%1], 16;"
                 :: "r"(dst), "l"(src) : "memory");
}
__device__ __forceinline__ void cp_commit() {
    asm volatile("cp.async.commit_group;" ::: "memory");
}
__device__ __forceinline__ void cp_wait1() {
    asm volatile("cp.async.wait_group 1;" ::: "memory");
}
__device__ __forceinline__ void ldmx4(uint32_t* r, uint32_t addr) {
    asm volatile("ldmatrix.sync.aligned.m8n8.x4.shared.b16 {%0,%1,%2,%3}, [%4];"
                 : "=r"(r[0]), "=r"(r[1]), "=r"(r[2]), "=r"(r[3]) : "r"(addr));
}
__device__ __forceinline__ void mma16816(float* d, const uint32_t* a,
                                         uint32_t b0, uint32_t b1) {
    asm volatile(
        "mma.sync.aligned.m16n8k16.row.col.f32.f16.f16.f32 "
        "{%0,%1,%2,%3}, {%4,%5,%6,%7}, {%8,%9}, {%0,%1,%2,%3};"
        : "+f"(d[0]), "+f"(d[1]), "+f"(d[2]), "+f"(d[3])
        : "r"(a[0]), "r"(a[1]), "r"(a[2]), "r"(a[3]), "r"(b0), "r"(b1));
}
__device__ __forceinline__ uint32_t pack2(float a, float b) {
    __half2 h = __floats2half2_rn(a, b);
    return *reinterpret_cast<uint32_t*>(&h);
}

// ---------------------------------------------------------------------------
// Prep kernel: z=0 enc proj, z=1 dec proj, z=2 W transpose+fp16 convert.
// Proj: C[M,N] = A[M,K] @ W[K,N] (+bias), 64x64 tile, BK=16, reg prefetch.
// ---------------------------------------------------------------------------
__global__ __launch_bounds__(256, 2) void prep_kernel(
    const float* __restrict__ enc_out, const float* __restrict__ dec_out,
    const float* __restrict__ W_enc, const float* __restrict__ b_enc,
    const float* __restrict__ W_dec, const float* __restrict__ W_out)
{
    int z = blockIdx.z;
    int tid = threadIdx.x;

    if (z == 2) {   // g_Wt[v][k] = fp16(W_out[k][v]); 128 blocks x 5 v-rows
        int bid = blockIdx.y * 8 + blockIdx.x;
        #pragma unroll
        for (int vv = 0; vv < 5; vv++) {
            int v = bid * 5 + vv;
            for (int k = tid; k < Hc; k += 256)
                g_Wt[(size_t)v * Hc + k] = __float2half_rn(W_out[(size_t)k * Vc + v]);
        }
        return;
    }

    const float* A; const float* W; const float* bias; float* C; int K;
    if (z == 0) {
        A = enc_out; W = W_enc; bias = b_enc; K = Ec;
        float* p; asm("cvta.global.u64 %0, g_enc;" : "=l"(p)); C = p;
    } else {
        if (blockIdx.y >= 8) return;
        A = dec_out; W = W_dec; bias = nullptr; K = Dc;
        float* p; asm("cvta.global.u64 %0, g_dec;" : "=l"(p)); C = p;
    }
    const int N = Hc;

    __shared__ float As[16][64];
    __shared__ float Ws[16][64];
    int row0 = blockIdx.y * 64, col0 = blockIdx.x * 64;
    int tx = tid & 15, ty = tid >> 4;
    float acc[4][4] = {};

    int rA = tid >> 2, kqA = (tid & 3) * 4;
    int kW = tid >> 4, cqW = (tid & 15) * 4;

    float4 areg = *(const float4*)&A[(size_t)(row0 + rA) * K + kqA];
    float4 wreg = *(const float4*)&W[(size_t)kW * N + col0 + cqW];

    const int NK = K / 16;
    for (int kt = 0; kt < NK; kt++) {
        __syncthreads();
        As[kqA + 0][rA] = areg.x;
        As[kqA + 1][rA] = areg.y;
        As[kqA + 2][rA] = areg.z;
        As[kqA + 3][rA] = areg.w;
        *(float4*)&Ws[kW][cqW] = wreg;
        __syncthreads();
        if (kt + 1 < NK) {
            int k0 = (kt + 1) * 16;
            areg = *(const float4*)&A[(size_t)(row0 + rA) * K + k0 + kqA];
            wreg = *(const float4*)&W[(size_t)(k0 + kW) * N + col0 + cqW];
        }
        #pragma unroll
        for (int kk = 0; kk < 16; kk++) {
            float a[4], b[4];
            #pragma unroll
            for (int i = 0; i < 4; i++) a[i] = As[kk][ty * 4 + i];
            #pragma unroll
            for (int j = 0; j < 4; j++) b[j] = Ws[kk][tx * 4 + j];
            #pragma unroll
            for (int i = 0; i < 4; i++)
                #pragma unroll
                for (int j = 0; j < 4; j++)
                    acc[i][j] += a[i] * b[j];
        }
    }
    #pragma unroll
    for (int i = 0; i < 4; i++) {
        int r = row0 + ty * 4 + i;
        #pragma unroll
        for (int j = 0; j < 4; j++) {
            int c = col0 + tx * 4 + j;
            float v = acc[i][j];
            if (bias) v += bias[c];
            C[(size_t)r * N + c] = v;
        }
    }
}

// ---------------------------------------------------------------------------
// Fused joint kernel: one CTA per (b,t).
//   A[128u x 512k] = fp16(tanh(enc+dec)) built once in SMEM (8 chunks, JIT
//   during v-tile 0, chunk k+1's tanh issued after chunk k's MMAs).
//   W streamed as 40 chunks [128v x 64k] via 3-buf cp.async ring, distance 2.
//   16 warps, warp tile 32x32, m16n8k16 fp16->fp32, acc init from bias.
// ---------------------------------------------------------------------------
#define CHKB 16384                 // one chunk: 128 rows x 64 halfs
#define W_OFF (8 * CHKB)           // A = 8 chunks = 128KB
#define JSMEM (W_OFF + 3 * CHKB)   // 180224 B

struct JCtx {
    uint32_t sb;
    const float* encR;
    const float* decB;
};

__device__ __forceinline__ void fillA(const JCtx& c, int k, int tid) {
    int K0 = k * 64;
    #pragma unroll
    for (int i = 0; i < 2; i++) {
        int idx = tid + i * 512;           // 1024 units of 8 halfs
        int r = idx >> 3, kg = idx & 7;
        int kc = K0 + kg * 8;
        float4 d0 = *(const float4*)(c.decB + (size_t)r * Hc + kc);
        float4 d1 = *(const float4*)(c.decB + (size_t)r * Hc + kc + 4);
        float4 e0 = *(const float4*)(c.encR + kc);
        float4 e1 = *(const float4*)(c.encR + kc + 4);
        uint4 q;
        q.x = pack2(tanhf(d0.x + e0.x), tanhf(d0.y + e0.y));
        q.y = pack2(tanhf(d0.z + e0.z), tanhf(d0.w + e0.w));
        q.z = pack2(tanhf(d1.x + e1.x), tanhf(d1.y + e1.y));
        q.w = pack2(tanhf(d1.z + e1.z), tanhf(d1.w + e1.w));
        uint32_t off = (uint32_t)k * CHKB + r * 128 + (((uint32_t)kg * 16) ^ ((r & 7) << 4));
        asm volatile("st.shared.v4.b32 [%0], {%1,%2,%3,%4};"
                     :: "r"(c.sb + off), "r"(q.x), "r"(q.y), "r"(q.z), "r"(q.w)
                     : "memory");
    }
}

__device__ __forceinline__ void loadW(uint32_t sb, int cc, int tid) {
    int v0 = (cc >> 3) * 128, K0 = (cc & 7) * 64;
    uint32_t dstb = sb + W_OFF + (cc % 3) * CHKB;
    const __half* src = g_Wt + (size_t)v0 * Hc + K0;
    #pragma unroll
    for (int i = 0; i < 2; i++) {
        int idx = tid + i * 512;
        int r = idx >> 3, kg = idx & 7;
        cp16(dstb + r * 128 + (((uint32_t)kg * 16) ^ ((r & 7) << 4)),
             src + (size_t)r * Hc + kg * 8);
    }
}

__global__ __launch_bounds__(512, 1) void joint_kernel(
    const float* __restrict__ bout, float* __restrict__ out)
{
    extern __shared__ char smem[];
    JCtx c;
    c.sb = smem_u32(smem);
    int tid = threadIdx.x, l = tid & 31, w = tid >> 5;
    int bt = blockIdx.x, b = bt >> 8;
    c.encR = g_enc + (size_t)bt * Hc;
    c.decB = g_dec + (size_t)b * Uc * Hc;

    int m0 = (w >> 2) * 32, n0 = (w & 3) * 32;
    int rowA = l & 15, khA = (l >> 4) * 16;
    int rowB = (l & 7) + ((l >> 4) << 3), khB = ((l >> 3) & 1) * 16;
    int gr = l >> 2, ct = l & 3;

    // Prologue: W chunks 0,1 in flight; A chunk 0 computed.
    loadW(c.sb, 0, tid); cp_commit();
    loadW(c.sb, 1, tid); cp_commit();
    fillA(c, 0, tid);

    float acc[2][4][4];
    float* outbt = out + (size_t)bt * (Uc * Vc);

    for (int i = 0; i < 40; i++) {
        int v = i >> 3, k = i & 7;
        cp_wait1();
        __syncthreads();   // W chunk i visible; A chunk k visible (v==0)

        if (k == 0) {   // init accumulators from bias
            #pragma unroll
            for (int nf = 0; nf < 4; nf++) {
                int cc = (v << 7) + n0 + nf * 8 + 2 * ct;
                float b0 = bout[cc], b1 = bout[cc + 1];
                #pragma unroll
                for (int mf = 0; mf < 2; mf++) {
                    acc[mf][nf][0] = b0; acc[mf][nf][1] = b1;
                    acc[mf][nf][2] = b0; acc[mf][nf][3] = b1;
                }
            }
        }

        uint32_t Ab = c.sb + (uint32_t)k * CHKB;
        uint32_t Wb = c.sb + W_OFF + (uint32_t)(i % 3) * CHKB;
        #pragma unroll
        for (int ks = 0; ks < 4; ks++) {
            uint32_t a[2][4], bb[2][4];
            #pragma unroll
            for (int mf = 0; mf < 2; mf++) {
                int r = m0 + mf * 16 + rowA;
                ldmx4(a[mf], Ab + r * 128 + (((uint32_t)(ks * 32 + khA)) ^ ((r & 7) << 4)));
            }
            #pragma unroll
            for (int nb = 0; nb < 2; nb++) {
                int r = n0 + nb * 16 + rowB;
                ldmx4(bb[nb], Wb + r * 128 + (((uint32_t)(ks * 32 + khB)) ^ ((r & 7) << 4)));
            }
            #pragma unroll
            for (int mf = 0; mf < 2; mf++)
                #pragma unroll
                for (int nf = 0; nf < 4; nf++)
                    mma16816(acc[mf][nf], a[mf],
                             bb[nf >> 1][2 * (nf & 1)], bb[nf >> 1][2 * (nf & 1) + 1]);
        }

        if (v == 0 && k < 7) fillA(c, k + 1, tid);   // hidden under MMA
        if (i + 2 < 40) loadW(c.sb, i + 2, tid);
        cp_commit();   // empty group near tail keeps wait_group bookkeeping uniform

        if (k == 7) {   // epilogue for v-tile (bias already in acc)
            #pragma unroll
            for (int nf = 0; nf < 4; nf++) {
                int cc = (v << 7) + n0 + nf * 8 + 2 * ct;
                #pragma unroll
                for (int mf = 0; mf < 2; mf++) {
                    int u = m0 + mf * 16 + gr;
                    float* p = outbt + (size_t)u * Vc + cc;
                    float2 t0; t0.x = acc[mf][nf][0]; t0.y = acc[mf][nf][1];
                    float2 t1; t1.x = acc[mf][nf][2]; t1.y = acc[mf][nf][3];
                    *(float2*)p = t0;
                    *(float2*)(p + 8 * Vc) = t1;
                }
            }
        }
    }
}

// ---------------------------------------------------------------------------
extern "C" void kernel_launch(void* const* d_in, const int* in_sizes, int n_in,
                              void* d_out, int out_size)
{
    const float* enc_out = (const float*)d_in[0];
    const float* dec_out = (const float*)d_in[1];
    const float* W_enc   = (const float*)d_in[2];
    const float* b_enc   = (const float*)d_in[3];
    const float* W_dec   = (const float*)d_in[4];
    const float* W_out   = (const float*)d_in[5];
    const float* b_out   = (const float*)d_in[6];
    float* out = (float*)d_out;

    cudaFuncSetAttribute(joint_kernel,
                         cudaFuncAttributeMaxDynamicSharedMemorySize, JSMEM);

    prep_kernel<<<dim3(8, 16, 3), 256>>>(enc_out, dec_out, W_enc, b_enc, W_dec, W_out);
    joint_kernel<<<Bc * Tc, 512, JSMEM>>>(b_out, out);
}

// round 5
// speedup vs baseline: 1.0852x; 1.0852x over previous
#include <cuda_runtime.h>
#include <cuda_fp16.h>
#include <math.h>
#include <stdint.h>

#define Bc 4
#define Tc 256
#define Uc 128
#define Ec 512
#define Dc 640
#define Hc 512
#define Vc 640

// Scratch (no cudaMalloc allowed).
__device__ float  g_enc[Bc * Tc * Hc];   // [B*T, H]
__device__ float  g_dec[Bc * Uc * Hc];   // [B*U, H]
__device__ __half g_Wt[Vc * Hc];         // W_out^T fp16: [V, H]

// ---------------------------------------------------------------------------
// Helpers (sm_80-era PTX only — no 'a'-gated instructions)
// ---------------------------------------------------------------------------
__device__ __forceinline__ uint32_t smem_u32(const void* p) {
    return (uint32_t)__cvta_generic_to_shared(p);
}
__device__ __forceinline__ void cp16(uint32_t dst, const void* src) {
    asm volatile("cp.async.cg.shared.global [%0], [%1], 16;"
                 :: "r"(dst), "l"(src) : "memory");
}
__device__ __forceinline__ void cp_commit() {
    asm volatile("cp.async.commit_group;" ::: "memory");
}
__device__ __forceinline__ void cp_wait1() {
    asm volatile("cp.async.wait_group 1;" ::: "memory");
}
__device__ __forceinline__ void ldmx4(uint32_t* r, uint32_t addr) {
    asm volatile("ldmatrix.sync.aligned.m8n8.x4.shared.b16 {%0,%1,%2,%3}, [%4];"
                 : "=r"(r[0]), "=r"(r[1]), "=r"(r[2]), "=r"(r[3]) : "r"(addr));
}
__device__ __forceinline__ void mma16816(float* d, const uint32_t* a,
                                         uint32_t b0, uint32_t b1) {
    asm volatile(
        "mma.sync.aligned.m16n8k16.row.col.f32.f16.f16.f32 "
        "{%0,%1,%2,%3}, {%4,%5,%6,%7}, {%8,%9}, {%0,%1,%2,%3};"
        : "+f"(d[0]), "+f"(d[1]), "+f"(d[2]), "+f"(d[3])
        : "r"(a[0]), "r"(a[1]), "r"(a[2]), "r"(a[3]), "r"(b0), "r"(b1));
}
__device__ __forceinline__ uint32_t pack2(float a, float b) {
    __half2 h = __floats2half2_rn(a, b);
    return *reinterpret_cast<uint32_t*>(&h);
}

// ---------------------------------------------------------------------------
// Prep kernel: z=0 enc proj, z=1 dec proj, z=2 W transpose+fp16 convert.
// ---------------------------------------------------------------------------
__global__ __launch_bounds__(256, 2) void prep_kernel(
    const float* __restrict__ enc_out, const float* __restrict__ dec_out,
    const float* __restrict__ W_enc, const float* __restrict__ b_enc,
    const float* __restrict__ W_dec, const float* __restrict__ W_out)
{
    int z = blockIdx.z;
    int tid = threadIdx.x;

    if (z == 2) {   // g_Wt[v][k] = fp16(W_out[k][v]); 128 blocks x 5 v-rows
        int bid = blockIdx.y * 8 + blockIdx.x;
        #pragma unroll
        for (int vv = 0; vv < 5; vv++) {
            int v = bid * 5 + vv;
            for (int k = tid; k < Hc; k += 256)
                g_Wt[(size_t)v * Hc + k] = __float2half_rn(W_out[(size_t)k * Vc + v]);
        }
        return;
    }

    const float* A; const float* W; const float* bias; float* C; int K;
    if (z == 0) {
        A = enc_out; W = W_enc; bias = b_enc; K = Ec;
        float* p; asm("cvta.global.u64 %0, g_enc;" : "=l"(p)); C = p;
    } else {
        if (blockIdx.y >= 8) return;
        A = dec_out; W = W_dec; bias = nullptr; K = Dc;
        float* p; asm("cvta.global.u64 %0, g_dec;" : "=l"(p)); C = p;
    }
    const int N = Hc;

    __shared__ float As[16][64];
    __shared__ float Ws[16][64];
    int row0 = blockIdx.y * 64, col0 = blockIdx.x * 64;
    int tx = tid & 15, ty = tid >> 4;
    float acc[4][4] = {};

    int rA = tid >> 2, kqA = (tid & 3) * 4;
    int kW = tid >> 4, cqW = (tid & 15) * 4;

    float4 areg = *(const float4*)&A[(size_t)(row0 + rA) * K + kqA];
    float4 wreg = *(const float4*)&W[(size_t)kW * N + col0 + cqW];

    const int NK = K / 16;
    for (int kt = 0; kt < NK; kt++) {
        __syncthreads();
        As[kqA + 0][rA] = areg.x;
        As[kqA + 1][rA] = areg.y;
        As[kqA + 2][rA] = areg.z;
        As[kqA + 3][rA] = areg.w;
        *(float4*)&Ws[kW][cqW] = wreg;
        __syncthreads();
        if (kt + 1 < NK) {
            int k0 = (kt + 1) * 16;
            areg = *(const float4*)&A[(size_t)(row0 + rA) * K + k0 + kqA];
            wreg = *(const float4*)&W[(size_t)(k0 + kW) * N + col0 + cqW];
        }
        #pragma unroll
        for (int kk = 0; kk < 16; kk++) {
            float a[4], b[4];
            #pragma unroll
            for (int i = 0; i < 4; i++) a[i] = As[kk][ty * 4 + i];
            #pragma unroll
            for (int j = 0; j < 4; j++) b[j] = Ws[kk][tx * 4 + j];
            #pragma unroll
            for (int i = 0; i < 4; i++)
                #pragma unroll
                for (int j = 0; j < 4; j++)
                    acc[i][j] += a[i] * b[j];
        }
    }
    #pragma unroll
    for (int i = 0; i < 4; i++) {
        int r = row0 + ty * 4 + i;
        #pragma unroll
        for (int j = 0; j < 4; j++) {
            int c = col0 + tx * 4 + j;
            float v = acc[i][j];
            if (bias) v += bias[c];
            C[(size_t)r * N + c] = v;
        }
    }
}

// ---------------------------------------------------------------------------
// Fused joint kernel: one CTA per (b,t), 256 threads (8 warps).
//   A[128u x 512k] fp16(tanh(enc+dec)) resident in SMEM, filled JIT in vtile0.
//   v-tiles: 256, 256, 128. W chunk = [Ntile x 64k] via 3-buf cp.async ring.
//   Warp tile 64x64 (2m x 4n grid), m16n8k16 fp16->fp32, acc init from bias.
// ---------------------------------------------------------------------------
#define ACHK 16384                  // A chunk: 128 rows x 64 halfs
#define WCH  32768                  // W chunk buffer: 256 rows x 64 halfs
#define W_OFF (8 * ACHK)            // A = 128KB
#define JSMEM (W_OFF + 3 * WCH)     // 229376 B
#define NIT 24

struct JCtx {
    uint32_t sb;
    const float* encR;
    const float* decB;
};

__device__ __forceinline__ void fillA(const JCtx& c, int k, int tid) {
    int K0 = k * 64;
    #pragma unroll
    for (int i = 0; i < 4; i++) {
        int idx = tid + i * 256;           // 1024 units of 8 halfs
        int r = idx >> 3, kg = idx & 7;
        int kc = K0 + kg * 8;
        float4 d0 = *(const float4*)(c.decB + (size_t)r * Hc + kc);
        float4 d1 = *(const float4*)(c.decB + (size_t)r * Hc + kc + 4);
        float4 e0 = *(const float4*)(c.encR + kc);
        float4 e1 = *(const float4*)(c.encR + kc + 4);
        uint4 q;
        q.x = pack2(tanhf(d0.x + e0.x), tanhf(d0.y + e0.y));
        q.y = pack2(tanhf(d0.z + e0.z), tanhf(d0.w + e0.w));
        q.z = pack2(tanhf(d1.x + e1.x), tanhf(d1.y + e1.y));
        q.w = pack2(tanhf(d1.z + e1.z), tanhf(d1.w + e1.w));
        uint32_t off = (uint32_t)k * ACHK + r * 128 + (((uint32_t)kg * 16) ^ ((r & 7) << 4));
        asm volatile("st.shared.v4.b32 [%0], {%1,%2,%3,%4};"
                     :: "r"(c.sb + off), "r"(q.x), "r"(q.y), "r"(q.z), "r"(q.w)
                     : "memory");
    }
}

// Load W chunk i (vt = i>>3, k = i&7) into ring buffer i%3.
__device__ __forceinline__ void loadW(uint32_t sb, int i, int tid) {
    int vt = i >> 3, k = i & 7;
    int rows = (vt == 2) ? 128 : 256;
    uint32_t dstb = sb + W_OFF + (uint32_t)(i % 3) * WCH;
    const __half* src = g_Wt + ((size_t)vt * 256) * Hc + k * 64;
    int nu = rows * 8;
    for (int idx = tid; idx < nu; idx += 256) {
        int r = idx >> 3, kg = idx & 7;
        cp16(dstb + r * 128 + (((uint32_t)kg * 16) ^ ((r & 7) << 4)),
             src + (size_t)r * Hc + kg * 8);
    }
}

__global__ __launch_bounds__(256, 1) void joint_kernel(
    const float* __restrict__ bout, float* __restrict__ out)
{
    extern __shared__ char smem[];
    JCtx c;
    c.sb = smem_u32(smem);
    int tid = threadIdx.x, l = tid & 31, w = tid >> 5;
    int bt = blockIdx.x, b = bt >> 8;
    c.encR = g_enc + (size_t)bt * Hc;
    c.decB = g_dec + (size_t)b * Uc * Hc;

    int m0 = (w & 1) * 64;          // 0 / 64
    int n0 = (w >> 1) * 64;         // 0 / 64 / 128 / 192
    int rowA = l & 15, khA = (l >> 4) * 16;
    int rowB = (l & 7) + ((l >> 4) << 3), khB = ((l >> 3) & 1) * 16;
    int gr = l >> 2, ct = l & 3;

    // Prologue: W chunks 0,1 in flight; A chunk 0 computed.
    loadW(c.sb, 0, tid); cp_commit();
    loadW(c.sb, 1, tid); cp_commit();
    fillA(c, 0, tid);

    float acc[4][8][4];
    float* outbt = out + (size_t)bt * (Uc * Vc);

    for (int i = 0; i < NIT; i++) {
        int vt = i >> 3, k = i & 7;
        int Ntile = (vt == 2) ? 128 : 256;
        bool active = n0 < Ntile;
        cp_wait1();
        __syncthreads();   // W chunk i visible; A chunk k visible (vt==0)

        if (k == 0 && active) {   // init accumulators from bias
            #pragma unroll
            for (int nf = 0; nf < 8; nf++) {
                int cc = vt * 256 + n0 + nf * 8 + 2 * ct;
                float b0 = bout[cc], b1 = bout[cc + 1];
                #pragma unroll
                for (int mf = 0; mf < 4; mf++) {
                    acc[mf][nf][0] = b0; acc[mf][nf][1] = b1;
                    acc[mf][nf][2] = b0; acc[mf][nf][3] = b1;
                }
            }
        }

        if (active) {
            uint32_t Ab = c.sb + (uint32_t)k * ACHK;
            uint32_t Wb = c.sb + W_OFF + (uint32_t)(i % 3) * WCH;
            #pragma unroll
            for (int ks = 0; ks < 4; ks++) {
                uint32_t a[4][4], bq[4][4];
                #pragma unroll
                for (int mf = 0; mf < 4; mf++) {
                    int r = m0 + mf * 16 + rowA;
                    ldmx4(a[mf], Ab + r * 128 + (((uint32_t)(ks * 32 + khA)) ^ ((r & 7) << 4)));
                }
                #pragma unroll
                for (int nb = 0; nb < 4; nb++) {
                    int r = n0 + nb * 16 + rowB;
                    ldmx4(bq[nb], Wb + r * 128 + (((uint32_t)(ks * 32 + khB)) ^ ((r & 7) << 4)));
                }
                #pragma unroll
                for (int mf = 0; mf < 4; mf++)
                    #pragma unroll
                    for (int nf = 0; nf < 8; nf++)
                        mma16816(acc[mf][nf], a[mf],
                                 bq[nf >> 1][2 * (nf & 1)], bq[nf >> 1][2 * (nf & 1) + 1]);
            }
        }

        if (vt == 0 && k < 7) fillA(c, k + 1, tid);   // hidden under MMA
        if (i + 2 < NIT) loadW(c.sb, i + 2, tid);
        cp_commit();   // uniform commit keeps wait_group bookkeeping simple

        if (k == 7 && active) {   // epilogue for v-tile (bias already in acc)
            #pragma unroll
            for (int nf = 0; nf < 8; nf++) {
                int cc = vt * 256 + n0 + nf * 8 + 2 * ct;
                #pragma unroll
                for (int mf = 0; mf < 4; mf++) {
                    int u = m0 + mf * 16 + gr;
                    float* p = outbt + (size_t)u * Vc + cc;
                    float2 t0; t0.x = acc[mf][nf][0]; t0.y = acc[mf][nf][1];
                    float2 t1; t1.x = acc[mf][nf][2]; t1.y = acc[mf][nf][3];
                    *(float2*)p = t0;
                    *(float2*)(p + 8 * Vc) = t1;
                }
            }
        }
    }
}

// ---------------------------------------------------------------------------
extern "C" void kernel_launch(void* const* d_in, const int* in_sizes, int n_in,
                              void* d_out, int out_size)
{
    const float* enc_out = (const float*)d_in[0];
    const float* dec_out = (const float*)d_in[1];
    const float* W_enc   = (const float*)d_in[2];
    const float* b_enc   = (const float*)d_in[3];
    const float* W_dec   = (const float*)d_in[4];
    const float* W_out   = (const float*)d_in[5];
    const float* b_out   = (const float*)d_in[6];
    float* out = (float*)d_out;

    cudaFuncSetAttribute(joint_kernel,
                         cudaFuncAttributeMaxDynamicSharedMemorySize, JSMEM);

    prep_kernel<<<dim3(8, 16, 3), 256>>>(enc_out, dec_out, W_enc, b_enc, W_dec, W_out);
    joint_kernel<<<Bc * Tc, 256, JSMEM>>>(b_out, out);
}

// round 6
// speedup vs baseline: 1.1440x; 1.0541x over previous
#include <cuda_runtime.h>
#include <cuda_fp16.h>
#include <math.h>
#include <stdint.h>

#define Bc 4
#define Tc 256
#define Uc 128
#define Ec 512
#define Dc 640
#define Hc 512
#define Vc 640

// Scratch (no cudaMalloc allowed).
__device__ float  g_enc[Bc * Tc * Hc];   // [B*T, H]
__device__ float  g_dec[Bc * Uc * Hc];   // [B*U, H]
__device__ __half g_Wt[Vc * Hc];         // W_out^T fp16: [V, H]

// ---------------------------------------------------------------------------
// Helpers (sm_80-era PTX only — no 'a'-gated instructions)
// ---------------------------------------------------------------------------
__device__ __forceinline__ uint32_t smem_u32(const void* p) {
    return (uint32_t)__cvta_generic_to_shared(p);
}
__device__ __forceinline__ void cp16(uint32_t dst, const void* src) {
    asm volatile("cp.async.cg.shared.global [%0], [%1], 16;"
                 :: "r"(dst), "l"(src) : "memory");
}
__device__ __forceinline__ void cp_commit() {
    asm volatile("cp.async.commit_group;" ::: "memory");
}
__device__ __forceinline__ void cp_wait1() {
    asm volatile("cp.async.wait_group 1;" ::: "memory");
}
__device__ __forceinline__ void ldmx4(uint32_t* r, uint32_t addr) {
    asm volatile("ldmatrix.sync.aligned.m8n8.x4.shared.b16 {%0,%1,%2,%3}, [%4];"
                 : "=r"(r[0]), "=r"(r[1]), "=r"(r[2]), "=r"(r[3]) : "r"(addr));
}
__device__ __forceinline__ void mma16816(float* d, const uint32_t* a,
                                         uint32_t b0, uint32_t b1) {
    asm volatile(
        "mma.sync.aligned.m16n8k16.row.col.f32.f16.f16.f32 "
        "{%0,%1,%2,%3}, {%4,%5,%6,%7}, {%8,%9}, {%0,%1,%2,%3};"
        : "+f"(d[0]), "+f"(d[1]), "+f"(d[2]), "+f"(d[3])
        : "r"(a[0]), "r"(a[1]), "r"(a[2]), "r"(a[3]), "r"(b0), "r"(b1));
}
__device__ __forceinline__ float tanh_fast(float x) {
    asm("tanh.approx.f32 %0, %0;" : "+f"(x));
    return x;
}
__device__ __forceinline__ uint32_t pack2(float a, float b) {
    __half2 h = __floats2half2_rn(a, b);
    return *reinterpret_cast<uint32_t*>(&h);
}

// ---------------------------------------------------------------------------
// Prep kernel: z=0 enc proj, z=1 dec proj, z=2 W transpose+fp16 (tiled).
// ---------------------------------------------------------------------------
__global__ __launch_bounds__(256, 2) void prep_kernel(
    const float* __restrict__ enc_out, const float* __restrict__ dec_out,
    const float* __restrict__ W_enc, const float* __restrict__ b_enc,
    const float* __restrict__ W_dec, const float* __restrict__ W_out)
{
    int z = blockIdx.z;
    int tid = threadIdx.x;

    if (z == 2) {   // coalesced tiled transpose: g_Wt[v][k] = fp16(W_out[k][v])
        __shared__ float t[32][33];
        int bid = blockIdx.y * 8 + blockIdx.x;     // 128 blocks
        int r0 = tid >> 5, cc = tid & 31;
        for (int tile = bid; tile < 320; tile += 128) {   // 16 kt x 20 vt
            int k0 = (tile / 20) * 32, v0 = (tile % 20) * 32;
            #pragma unroll
            for (int i = 0; i < 4; i++) {
                int r = r0 + i * 8;
                t[r][cc] = W_out[(size_t)(k0 + r) * Vc + v0 + cc];
            }
            __syncthreads();
            #pragma unroll
            for (int i = 0; i < 4; i++) {
                int r = r0 + i * 8;
                g_Wt[(size_t)(v0 + r) * Hc + k0 + cc] = __float2half_rn(t[cc][r]);
            }
            __syncthreads();
        }
        return;
    }

    const float* A; const float* W; const float* bias; float* C; int K;
    if (z == 0) {
        A = enc_out; W = W_enc; bias = b_enc; K = Ec;
        float* p; asm("cvta.global.u64 %0, g_enc;" : "=l"(p)); C = p;
    } else {
        if (blockIdx.y >= 8) return;
        A = dec_out; W = W_dec; bias = nullptr; K = Dc;
        float* p; asm("cvta.global.u64 %0, g_dec;" : "=l"(p)); C = p;
    }
    const int N = Hc;

    __shared__ float As[16][64];
    __shared__ float Ws[16][64];
    int row0 = blockIdx.y * 64, col0 = blockIdx.x * 64;
    int tx = tid & 15, ty = tid >> 4;
    float acc[4][4] = {};

    int rA = tid >> 2, kqA = (tid & 3) * 4;
    int kW = tid >> 4, cqW = (tid & 15) * 4;

    float4 areg = *(const float4*)&A[(size_t)(row0 + rA) * K + kqA];
    float4 wreg = *(const float4*)&W[(size_t)kW * N + col0 + cqW];

    const int NK = K / 16;
    for (int kt = 0; kt < NK; kt++) {
        __syncthreads();
        As[kqA + 0][rA] = areg.x;
        As[kqA + 1][rA] = areg.y;
        As[kqA + 2][rA] = areg.z;
        As[kqA + 3][rA] = areg.w;
        *(float4*)&Ws[kW][cqW] = wreg;
        __syncthreads();
        if (kt + 1 < NK) {
            int k0 = (kt + 1) * 16;
            areg = *(const float4*)&A[(size_t)(row0 + rA) * K + k0 + kqA];
            wreg = *(const float4*)&W[(size_t)(k0 + kW) * N + col0 + cqW];
        }
        #pragma unroll
        for (int kk = 0; kk < 16; kk++) {
            float a[4], b[4];
            #pragma unroll
            for (int i = 0; i < 4; i++) a[i] = As[kk][ty * 4 + i];
            #pragma unroll
            for (int j = 0; j < 4; j++) b[j] = Ws[kk][tx * 4 + j];
            #pragma unroll
            for (int i = 0; i < 4; i++)
                #pragma unroll
                for (int j = 0; j < 4; j++)
                    acc[i][j] += a[i] * b[j];
        }
    }
    #pragma unroll
    for (int i = 0; i < 4; i++) {
        int r = row0 + ty * 4 + i;
        #pragma unroll
        for (int j = 0; j < 4; j++) {
            int c = col0 + tx * 4 + j;
            float v = acc[i][j];
            if (bias) v += bias[c];
            C[(size_t)r * N + c] = v;
        }
    }
}

// ---------------------------------------------------------------------------
// Fused joint kernel: one CTA per (b,t), 256 threads (8 warps).
//   A[128u x 512k] fp16(tanh.approx(enc+dec)) resident in SMEM, filled JIT.
//   v-tiles: 256, 256, 128. W chunk via 3-buf cp.async ring, distance 2.
//   vt0/1: warp tile 64x64 (2m x 4n). vt2: warp tile 64x32 (2m x 4n) so all
//   warps stay active. m16n8k16 fp16->fp32, acc init from bias.
// ---------------------------------------------------------------------------
#define ACHK 16384                  // A chunk: 128 rows x 64 halfs
#define WCH  32768                  // W ring buffer stride
#define W_OFF (8 * ACHK)            // A = 128KB
#define JSMEM (W_OFF + 3 * WCH)     // 229376 B
#define NIT 24

struct JCtx {
    uint32_t sb;
    const float* encR;
    const float* decB;
};

__device__ __forceinline__ void fillA(const JCtx& c, int k, int tid) {
    int K0 = k * 64;
    #pragma unroll
    for (int i = 0; i < 4; i++) {
        int idx = tid + i * 256;           // 1024 units of 8 halfs
        int r = idx >> 3, kg = idx & 7;
        int kc = K0 + kg * 8;
        float4 d0 = *(const float4*)(c.decB + (size_t)r * Hc + kc);
        float4 d1 = *(const float4*)(c.decB + (size_t)r * Hc + kc + 4);
        float4 e0 = *(const float4*)(c.encR + kc);
        float4 e1 = *(const float4*)(c.encR + kc + 4);
        uint4 q;
        q.x = pack2(tanh_fast(d0.x + e0.x), tanh_fast(d0.y + e0.y));
        q.y = pack2(tanh_fast(d0.z + e0.z), tanh_fast(d0.w + e0.w));
        q.z = pack2(tanh_fast(d1.x + e1.x), tanh_fast(d1.y + e1.y));
        q.w = pack2(tanh_fast(d1.z + e1.z), tanh_fast(d1.w + e1.w));
        uint32_t off = (uint32_t)k * ACHK + r * 128 + (((uint32_t)kg * 16) ^ ((r & 7) << 4));
        asm volatile("st.shared.v4.b32 [%0], {%1,%2,%3,%4};"
                     :: "r"(c.sb + off), "r"(q.x), "r"(q.y), "r"(q.z), "r"(q.w)
                     : "memory");
    }
}

// Load W chunk i (vt = i>>3, k = i&7) into ring buffer i%3.
__device__ __forceinline__ void loadW(uint32_t sb, int i, int tid) {
    int vt = i >> 3, k = i & 7;
    int rows = (vt == 2) ? 128 : 256;
    uint32_t dstb = sb + W_OFF + (uint32_t)(i % 3) * WCH;
    const __half* src = g_Wt + ((size_t)vt * 256) * Hc + k * 64;
    int nu = rows * 8;
    for (int idx = tid; idx < nu; idx += 256) {
        int r = idx >> 3, kg = idx & 7;
        cp16(dstb + r * 128 + (((uint32_t)kg * 16) ^ ((r & 7) << 4)),
             src + (size_t)r * Hc + kg * 8);
    }
}

// One 64-K chunk of MMAs. NF = number of 8-wide N frags (8 for 64-wide, 4 for 32).
template<int NF>
__device__ __forceinline__ void mma_chunk(
    uint32_t Ab, uint32_t Wb, int m0, int n0,
    int rowA, int khA, int rowB, int khB, float acc[4][8][4])
{
    #pragma unroll
    for (int ks = 0; ks < 4; ks++) {
        uint32_t a[4][4], bq[NF / 2][4];
        #pragma unroll
        for (int mf = 0; mf < 4; mf++) {
            int r = m0 + mf * 16 + rowA;
            ldmx4(a[mf], Ab + r * 128 + (((uint32_t)(ks * 32 + khA)) ^ ((r & 7) << 4)));
        }
        #pragma unroll
        for (int nb = 0; nb < NF / 2; nb++) {
            int r = n0 + nb * 16 + rowB;
            ldmx4(bq[nb], Wb + r * 128 + (((uint32_t)(ks * 32 + khB)) ^ ((r & 7) << 4)));
        }
        #pragma unroll
        for (int mf = 0; mf < 4; mf++)
            #pragma unroll
            for (int nf = 0; nf < NF; nf++)
                mma16816(acc[mf][nf], a[mf],
                         bq[nf >> 1][2 * (nf & 1)], bq[nf >> 1][2 * (nf & 1) + 1]);
    }
}

__global__ __launch_bounds__(256, 1) void joint_kernel(
    const float* __restrict__ bout, float* __restrict__ out)
{
    extern __shared__ char smem[];
    JCtx c;
    c.sb = smem_u32(smem);
    int tid = threadIdx.x, l = tid & 31, w = tid >> 5;
    int bt = blockIdx.x, b = bt >> 8;
    c.encR = g_enc + (size_t)bt * Hc;
    c.decB = g_dec + (size_t)b * Uc * Hc;

    int m0 = (w & 1) * 64;            // 0 / 64
    int n0w = (w >> 1) * 64;          // vt0/1: 0/64/128/192
    int n0n = (w >> 1) * 32;          // vt2:   0/32/64/96
    int rowA = l & 15, khA = (l >> 4) * 16;
    int rowB = (l & 7) + ((l >> 4) << 3), khB = ((l >> 3) & 1) * 16;
    int gr = l >> 2, ct = l & 3;

    // Prologue: W chunks 0,1 in flight; A chunk 0 computed.
    loadW(c.sb, 0, tid); cp_commit();
    loadW(c.sb, 1, tid); cp_commit();
    fillA(c, 0, tid);

    float acc[4][8][4];
    float* outbt = out + (size_t)bt * (Uc * Vc);

    for (int i = 0; i < NIT; i++) {
        int vt = i >> 3, k = i & 7;
        bool wide = (vt < 2);
        int n0 = wide ? n0w : n0n;
        int NFc = wide ? 8 : 4;
        cp_wait1();
        __syncthreads();   // W chunk i visible; A chunk k visible (vt==0)

        if (k == 0) {   // init accumulators from bias
            #pragma unroll
            for (int nf = 0; nf < 8; nf++) {
                if (nf < NFc) {
                    int cc = vt * 256 + n0 + nf * 8 + 2 * ct;
                    float b0 = bout[cc], b1 = bout[cc + 1];
                    #pragma unroll
                    for (int mf = 0; mf < 4; mf++) {
                        acc[mf][nf][0] = b0; acc[mf][nf][1] = b1;
                        acc[mf][nf][2] = b0; acc[mf][nf][3] = b1;
                    }
                }
            }
        }

        uint32_t Ab = c.sb + (uint32_t)k * ACHK;
        uint32_t Wb = c.sb + W_OFF + (uint32_t)(i % 3) * WCH;
        if (wide)
            mma_chunk<8>(Ab, Wb, m0, n0, rowA, khA, rowB, khB, acc);
        else
            mma_chunk<4>(Ab, Wb, m0, n0, rowA, khA, rowB, khB, acc);

        if (vt == 0 && k < 7) fillA(c, k + 1, tid);   // hidden under MMA
        if (i + 2 < NIT) loadW(c.sb, i + 2, tid);
        cp_commit();   // uniform commit keeps wait_group bookkeeping simple

        if (k == 7) {   // epilogue for v-tile (bias already in acc)
            #pragma unroll
            for (int nf = 0; nf < 8; nf++) {
                if (nf < NFc) {
                    int cc = vt * 256 + n0 + nf * 8 + 2 * ct;
                    #pragma unroll
                    for (int mf = 0; mf < 4; mf++) {
                        int u = m0 + mf * 16 + gr;
                        float* p = outbt + (size_t)u * Vc + cc;
                        float2 t0; t0.x = acc[mf][nf][0]; t0.y = acc[mf][nf][1];
                        float2 t1; t1.x = acc[mf][nf][2]; t1.y = acc[mf][nf][3];
                        *(float2*)p = t0;
                        *(float2*)(p + 8 * Vc) = t1;
                    }
                }
            }
        }
    }
}

// ---------------------------------------------------------------------------
extern "C" void kernel_launch(void* const* d_in, const int* in_sizes, int n_in,
                              void* d_out, int out_size)
{
    const float* enc_out = (const float*)d_in[0];
    const float* dec_out = (const float*)d_in[1];
    const float* W_enc   = (const float*)d_in[2];
    const float* b_enc   = (const float*)d_in[3];
    const float* W_dec   = (const float*)d_in[4];
    const float* W_out   = (const float*)d_in[5];
    const float* b_out   = (const float*)d_in[6];
    float* out = (float*)d_out;

    cudaFuncSetAttribute(joint_kernel,
                         cudaFuncAttributeMaxDynamicSharedMemorySize, JSMEM);

    prep_kernel<<<dim3(8, 16, 3), 256>>>(enc_out, dec_out, W_enc, b_enc, W_dec, W_out);
    joint_kernel<<<Bc * Tc, 256, JSMEM>>>(b_out, out);
}

// round 7
// speedup vs baseline: 1.1638x; 1.0173x over previous
#include <cuda_runtime.h>
#include <cuda_fp16.h>
#include <math.h>
#include <stdint.h>

#define Bc 4
#define Tc 256
#define Uc 128
#define Ec 512
#define Dc 640
#define Hc 512
#define Vc 640

// Scratch (no cudaMalloc allowed).
__device__ float  g_enc[Bc * Tc * Hc];   // [B*T, H]
__device__ float  g_dec[Bc * Uc * Hc];   // [B*U, H]
__device__ __half g_Wt[Vc * Hc];         // W_out^T fp16: [V, H]

// ---------------------------------------------------------------------------
// Helpers (sm_80-era PTX only — no 'a'-gated instructions)
// ---------------------------------------------------------------------------
__device__ __forceinline__ uint32_t smem_u32(const void* p) {
    return (uint32_t)__cvta_generic_to_shared(p);
}
__device__ __forceinline__ void cp16(uint32_t dst, const void* src) {
    asm volatile("cp.async.cg.shared.global [%0], [%1], 16;"
                 :: "r"(dst), "l"(src) : "memory");
}
__device__ __forceinline__ void cp_commit() {
    asm volatile("cp.async.commit_group;" ::: "memory");
}
__device__ __forceinline__ void cp_wait1() {
    asm volatile("cp.async.wait_group 1;" ::: "memory");
}
__device__ __forceinline__ void bar_sync(int id, int cnt) {
    asm volatile("bar.sync %0, %1;" :: "r"(id), "r"(cnt) : "memory");
}
__device__ __forceinline__ void ldmx4(uint32_t* r, uint32_t addr) {
    asm volatile("ldmatrix.sync.aligned.m8n8.x4.shared.b16 {%0,%1,%2,%3}, [%4];"
                 : "=r"(r[0]), "=r"(r[1]), "=r"(r[2]), "=r"(r[3]) : "r"(addr));
}
__device__ __forceinline__ void mma16816(float* d, const uint32_t* a,
                                         uint32_t b0, uint32_t b1) {
    asm volatile(
        "mma.sync.aligned.m16n8k16.row.col.f32.f16.f16.f32 "
        "{%0,%1,%2,%3}, {%4,%5,%6,%7}, {%8,%9}, {%0,%1,%2,%3};"
        : "+f"(d[0]), "+f"(d[1]), "+f"(d[2]), "+f"(d[3])
        : "r"(a[0]), "r"(a[1]), "r"(a[2]), "r"(a[3]), "r"(b0), "r"(b1));
}
__device__ __forceinline__ float tanh_fast(float x) {
    asm("tanh.approx.f32 %0, %0;" : "+f"(x));
    return x;
}
__device__ __forceinline__ uint32_t pack2(float a, float b) {
    __half2 h = __floats2half2_rn(a, b);
    return *reinterpret_cast<uint32_t*>(&h);
}

// ---------------------------------------------------------------------------
// Prep kernel: z=0 enc proj, z=1 dec proj, z=2 W transpose+fp16 (tiled).
// ---------------------------------------------------------------------------
__global__ __launch_bounds__(256, 2) void prep_kernel(
    const float* __restrict__ enc_out, const float* __restrict__ dec_out,
    const float* __restrict__ W_enc, const float* __restrict__ b_enc,
    const float* __restrict__ W_dec, const float* __restrict__ W_out)
{
    int z = blockIdx.z;
    int tid = threadIdx.x;

    if (z == 2) {   // coalesced tiled transpose: g_Wt[v][k] = fp16(W_out[k][v])
        __shared__ float t[32][33];
        int bid = blockIdx.y * 8 + blockIdx.x;     // 128 blocks
        int r0 = tid >> 5, cc = tid & 31;
        for (int tile = bid; tile < 320; tile += 128) {   // 16 kt x 20 vt
            int k0 = (tile / 20) * 32, v0 = (tile % 20) * 32;
            #pragma unroll
            for (int i = 0; i < 4; i++) {
                int r = r0 + i * 8;
                t[r][cc] = W_out[(size_t)(k0 + r) * Vc + v0 + cc];
            }
            __syncthreads();
            #pragma unroll
            for (int i = 0; i < 4; i++) {
                int r = r0 + i * 8;
                g_Wt[(size_t)(v0 + r) * Hc + k0 + cc] = __float2half_rn(t[cc][r]);
            }
            __syncthreads();
        }
        return;
    }

    const float* A; const float* W; const float* bias; float* C; int K;
    if (z == 0) {
        A = enc_out; W = W_enc; bias = b_enc; K = Ec;
        float* p; asm("cvta.global.u64 %0, g_enc;" : "=l"(p)); C = p;
    } else {
        if (blockIdx.y >= 8) return;
        A = dec_out; W = W_dec; bias = nullptr; K = Dc;
        float* p; asm("cvta.global.u64 %0, g_dec;" : "=l"(p)); C = p;
    }
    const int N = Hc;

    __shared__ float As[16][64];
    __shared__ float Ws[16][64];
    int row0 = blockIdx.y * 64, col0 = blockIdx.x * 64;
    int tx = tid & 15, ty = tid >> 4;
    float acc[4][4] = {};

    int rA = tid >> 2, kqA = (tid & 3) * 4;
    int kW = tid >> 4, cqW = (tid & 15) * 4;

    float4 areg = *(const float4*)&A[(size_t)(row0 + rA) * K + kqA];
    float4 wreg = *(const float4*)&W[(size_t)kW * N + col0 + cqW];

    const int NK = K / 16;
    for (int kt = 0; kt < NK; kt++) {
        __syncthreads();
        As[kqA + 0][rA] = areg.x;
        As[kqA + 1][rA] = areg.y;
        As[kqA + 2][rA] = areg.z;
        As[kqA + 3][rA] = areg.w;
        *(float4*)&Ws[kW][cqW] = wreg;
        __syncthreads();
        if (kt + 1 < NK) {
            int k0 = (kt + 1) * 16;
            areg = *(const float4*)&A[(size_t)(row0 + rA) * K + k0 + kqA];
            wreg = *(const float4*)&W[(size_t)(k0 + kW) * N + col0 + cqW];
        }
        #pragma unroll
        for (int kk = 0; kk < 16; kk++) {
            float a[4], b[4];
            #pragma unroll
            for (int i = 0; i < 4; i++) a[i] = As[kk][ty * 4 + i];
            #pragma unroll
            for (int j = 0; j < 4; j++) b[j] = Ws[kk][tx * 4 + j];
            #pragma unroll
            for (int i = 0; i < 4; i++)
                #pragma unroll
                for (int j = 0; j < 4; j++)
                    acc[i][j] += a[i] * b[j];
        }
    }
    #pragma unroll
    for (int i = 0; i < 4; i++) {
        int r = row0 + ty * 4 + i;
        #pragma unroll
        for (int j = 0; j < 4; j++) {
            int c = col0 + tx * 4 + j;
            float v = acc[i][j];
            if (bias) v += bias[c];
            C[(size_t)r * N + c] = v;
        }
    }
}

// ---------------------------------------------------------------------------
// Fused joint kernel: one CTA per (b,t), 256 threads (8 warps), NO block-wide
// sync in the main loop.
//   Warp map: mgrp = w>>2 (m0 = mgrp*64), nw = w&3.
//   vt0/1: warp tile 64x64 (n0 = nw*64); vt2: 64x32 (n0 = nw*32).
//   W: each warp cp.asyncs ITS OWN n-rows (twins w/w+4 duplicate-write the same
//      addresses), gated by per-warp wait_group. 3-buf ring, distance 2.
//      Pair barrier (3+nw, 64 thr) before ring overwrite bounds twin drift.
//   A[128u x 512k] resident fp16(tanh.approx(enc+dec)); each m-group of 4
//      warps fills/consumes its own 64 rows; named barrier (1+mgrp, 128 thr)
//      only during vt0.
// ---------------------------------------------------------------------------
#define ACHK 16384                  // A chunk: 128 rows x 64 halfs
#define WCH  32768                  // W ring buffer stride
#define W_OFF (8 * ACHK)            // A = 128KB
#define JSMEM (W_OFF + 3 * WCH)     // 229376 B
#define NIT 24

struct JCtx {
    uint32_t sb;
    const float* encR;
    const float* decB;
};

// Fill A chunk k rows [m0, m0+64) — executed by one m-group (128 threads).
__device__ __forceinline__ void fillA_half(const JCtx& c, int k, int wtid, int m0) {
    int K0 = k * 64;
    #pragma unroll
    for (int i = 0; i < 4; i++) {
        int idx = i * 128 + wtid;          // 512 units of 8 halfs
        int r = m0 + (idx >> 3), kg = idx & 7;
        int kc = K0 + kg * 8;
        float4 d0 = *(const float4*)(c.decB + (size_t)r * Hc + kc);
        float4 d1 = *(const float4*)(c.decB + (size_t)r * Hc + kc + 4);
        float4 e0 = *(const float4*)(c.encR + kc);
        float4 e1 = *(const float4*)(c.encR + kc + 4);
        uint4 q;
        q.x = pack2(tanh_fast(d0.x + e0.x), tanh_fast(d0.y + e0.y));
        q.y = pack2(tanh_fast(d0.z + e0.z), tanh_fast(d0.w + e0.w));
        q.z = pack2(tanh_fast(d1.x + e1.x), tanh_fast(d1.y + e1.y));
        q.w = pack2(tanh_fast(d1.z + e1.z), tanh_fast(d1.w + e1.w));
        uint32_t off = (uint32_t)k * ACHK + r * 128 + (((uint32_t)kg * 16) ^ ((r & 7) << 4));
        asm volatile("st.shared.v4.b32 [%0], {%1,%2,%3,%4};"
                     :: "r"(c.sb + off), "r"(q.x), "r"(q.y), "r"(q.z), "r"(q.w)
                     : "memory");
    }
}

// Per-warp W load: chunk i (vt=i>>3, k=i&7), only this warp's n-rows.
__device__ __forceinline__ void loadW_warp(uint32_t sb, int i, int nw, int lane) {
    int vt = i >> 3, k = i & 7;
    int R = (vt == 2) ? 32 : 64;
    int rb = nw * R;
    uint32_t dstb = sb + W_OFF + (uint32_t)(i % 3) * WCH;
    const __half* src = g_Wt + ((size_t)(vt * 256 + rb)) * Hc + k * 64;
    #pragma unroll
    for (int j = 0; j < 2; j++) {
        #pragma unroll 8
        for (int idx = lane + j * 256; idx < ((j + 1) * 256); idx += 32) {
            if (idx < R * 8) {
                int r = rb + (idx >> 3), kg = idx & 7;
                cp16(dstb + r * 128 + (((uint32_t)kg * 16) ^ ((r & 7) << 4)),
                     src + (size_t)(idx >> 3) * Hc + kg * 8);
            }
        }
    }
}

// One 64-K chunk of MMAs. NF = number of 8-wide N frags (8 wide, 4 narrow).
template<int NF>
__device__ __forceinline__ void mma_chunk(
    uint32_t Ab, uint32_t Wb, int m0, int n0,
    int rowA, int khA, int rowB, int khB, float acc[4][8][4])
{
    #pragma unroll
    for (int ks = 0; ks < 4; ks++) {
        uint32_t a[4][4], bq[NF / 2][4];
        #pragma unroll
        for (int mf = 0; mf < 4; mf++) {
            int r = m0 + mf * 16 + rowA;
            ldmx4(a[mf], Ab + r * 128 + (((uint32_t)(ks * 32 + khA)) ^ ((r & 7) << 4)));
        }
        #pragma unroll
        for (int nb = 0; nb < NF / 2; nb++) {
            int r = n0 + nb * 16 + rowB;
            ldmx4(bq[nb], Wb + r * 128 + (((uint32_t)(ks * 32 + khB)) ^ ((r & 7) << 4)));
        }
        #pragma unroll
        for (int mf = 0; mf < 4; mf++)
            #pragma unroll
            for (int nf = 0; nf < NF; nf++)
                mma16816(acc[mf][nf], a[mf],
                         bq[nf >> 1][2 * (nf & 1)], bq[nf >> 1][2 * (nf & 1) + 1]);
    }
}

__global__ __launch_bounds__(256, 1) void joint_kernel(
    const float* __restrict__ bout, float* __restrict__ out)
{
    extern __shared__ char smem[];
    JCtx c;
    c.sb = smem_u32(smem);
    int tid = threadIdx.x, l = tid & 31, w = tid >> 5;
    int bt = blockIdx.x, b = bt >> 8;
    c.encR = g_enc + (size_t)bt * Hc;
    c.decB = g_dec + (size_t)b * Uc * Hc;

    int mgrp = w >> 2, nw = w & 3;
    int m0 = mgrp * 64;
    int wtid = tid & 127;
    int rowA = l & 15, khA = (l >> 4) * 16;
    int rowB = (l & 7) + ((l >> 4) << 3), khB = ((l >> 3) & 1) * 16;
    int gr = l >> 2, ct = l & 3;

    // Prologue: per-warp W chunks 0,1 in flight; own A half chunk 0 computed.
    loadW_warp(c.sb, 0, nw, l); cp_commit();
    loadW_warp(c.sb, 1, nw, l); cp_commit();
    fillA_half(c, 0, wtid, m0);

    float acc[4][8][4];
    float* outbt = out + (size_t)bt * (Uc * Vc);

    for (int i = 0; i < NIT; i++) {
        int vt = i >> 3, k = i & 7;
        bool wide = (vt < 2);
        int n0 = wide ? nw * 64 : nw * 32;
        int NFc = wide ? 8 : 4;

        cp_wait1();               // own W chunk i arrived
        __syncwarp();
        if (vt == 0) bar_sync(1 + mgrp, 128);   // own A chunk k ready

        if (k == 0) {   // init accumulators from bias
            #pragma unroll
            for (int nf = 0; nf < 8; nf++) {
                if (nf < NFc) {
                    int cc = vt * 256 + n0 + nf * 8 + 2 * ct;
                    float b0 = __ldg(&bout[cc]), b1 = __ldg(&bout[cc + 1]);
                    #pragma unroll
                    for (int mf = 0; mf < 4; mf++) {
                        acc[mf][nf][0] = b0; acc[mf][nf][1] = b1;
                        acc[mf][nf][2] = b0; acc[mf][nf][3] = b1;
                    }
                }
            }
        }

        uint32_t Ab = c.sb + (uint32_t)k * ACHK;
        uint32_t Wb = c.sb + W_OFF + (uint32_t)(i % 3) * WCH;
        if (wide)
            mma_chunk<8>(Ab, Wb, m0, n0, rowA, khA, rowB, khB, acc);
        else
            mma_chunk<4>(Ab, Wb, m0, n0, rowA, khA, rowB, khB, acc);

        if (vt == 0 && k < 7) fillA_half(c, k + 1, wtid, m0);  // hidden under MMA

        if (i + 2 < NIT) {
            bar_sync(3 + nw, 64);         // twin done reading buffer (i+2)%3
            loadW_warp(c.sb, i + 2, nw, l);
        }
        cp_commit();   // uniform per-warp group bookkeeping

        if (k == 7) {   // epilogue for v-tile (bias already in acc)
            #pragma unroll
            for (int nf = 0; nf < 8; nf++) {
                if (nf < NFc) {
                    int cc = vt * 256 + n0 + nf * 8 + 2 * ct;
                    #pragma unroll
                    for (int mf = 0; mf < 4; mf++) {
                        int u = m0 + mf * 16 + gr;
                        float* p = outbt + (size_t)u * Vc + cc;
                        float2 t0; t0.x = acc[mf][nf][0]; t0.y = acc[mf][nf][1];
                        float2 t1; t1.x = acc[mf][nf][2]; t1.y = acc[mf][nf][3];
                        *(float2*)p = t0;
                        *(float2*)(p + 8 * Vc) = t1;
                    }
                }
            }
        }
    }
}

// ---------------------------------------------------------------------------
extern "C" void kernel_launch(void* const* d_in, const int* in_sizes, int n_in,
                              void* d_out, int out_size)
{
    const float* enc_out = (const float*)d_in[0];
    const float* dec_out = (const float*)d_in[1];
    const float* W_enc   = (const float*)d_in[2];
    const float* b_enc   = (const float*)d_in[3];
    const float* W_dec   = (const float*)d_in[4];
    const float* W_out   = (const float*)d_in[5];
    const float* b_out   = (const float*)d_in[6];
    float* out = (float*)d_out;

    cudaFuncSetAttribute(joint_kernel,
                         cudaFuncAttributeMaxDynamicSharedMemorySize, JSMEM);

    prep_kernel<<<dim3(8, 16, 3), 256>>>(enc_out, dec_out, W_enc, b_enc, W_dec, W_out);
    joint_kernel<<<Bc * Tc, 256, JSMEM>>>(b_out, out);
}

// round 9
// speedup vs baseline: 1.1712x; 1.0064x over previous
#include <cuda_runtime.h>
#include <cuda_fp16.h>
#include <math.h>
#include <stdint.h>

#define Bc 4
#define Tc 256
#define Uc 128
#define Ec 512
#define Dc 640
#define Hc 512
#define Vc 640

// Scratch (no cudaMalloc allowed).
__device__ float  g_enc[Bc * Tc * Hc];   // [B*T, H]
__device__ float  g_dec[Bc * Uc * Hc];   // [B*U, H]
__device__ __half g_Wt[Vc * Hc];         // W_out^T fp16: [V, H]

// ---------------------------------------------------------------------------
// Helpers (sm_80-era PTX only — no 'a'-gated instructions)
// ---------------------------------------------------------------------------
__device__ __forceinline__ uint32_t smem_u32(const void* p) {
    return (uint32_t)__cvta_generic_to_shared(p);
}
__device__ __forceinline__ void cp16(uint32_t dst, const void* src) {
    asm volatile("cp.async.cg.shared.global [%0], [%1], 16;"
                 :: "r"(dst), "l"(src) : "memory");
}
__device__ __forceinline__ void cp_commit() {
    asm volatile("cp.async.commit_group;" ::: "memory");
}
__device__ __forceinline__ void cp_wait1() {
    asm volatile("cp.async.wait_group 1;" ::: "memory");
}
__device__ __forceinline__ void ldmx4(uint32_t* r, uint32_t addr) {
    asm volatile("ldmatrix.sync.aligned.m8n8.x4.shared.b16 {%0,%1,%2,%3}, [%4];"
                 : "=r"(r[0]), "=r"(r[1]), "=r"(r[2]), "=r"(r[3]) : "r"(addr));
}
__device__ __forceinline__ void mma16816(float* d, const uint32_t* a,
                                         uint32_t b0, uint32_t b1) {
    asm volatile(
        "mma.sync.aligned.m16n8k16.row.col.f32.f16.f16.f32 "
        "{%0,%1,%2,%3}, {%4,%5,%6,%7}, {%8,%9}, {%0,%1,%2,%3};"
        : "+f"(d[0]), "+f"(d[1]), "+f"(d[2]), "+f"(d[3])
        : "r"(a[0]), "r"(a[1]), "r"(a[2]), "r"(a[3]), "r"(b0), "r"(b1));
}
__device__ __forceinline__ float tanh_fast(float x) {
    asm("tanh.approx.f32 %0, %0;" : "+f"(x));
    return x;
}
__device__ __forceinline__ uint32_t pack2(float a, float b) {
    __half2 h = __floats2half2_rn(a, b);
    return *reinterpret_cast<uint32_t*>(&h);
}

// ---------------------------------------------------------------------------
// Prep kernel: z=0 enc proj, z=1 dec proj, z=2 W transpose+fp16 (tiled).
// ---------------------------------------------------------------------------
__global__ __launch_bounds__(256, 2) void prep_kernel(
    const float* __restrict__ enc_out, const float* __restrict__ dec_out,
    const float* __restrict__ W_enc, const float* __restrict__ b_enc,
    const float* __restrict__ W_dec, const float* __restrict__ W_out)
{
    int z = blockIdx.z;
    int tid = threadIdx.x;

    if (z == 2) {   // coalesced tiled transpose: g_Wt[v][k] = fp16(W_out[k][v])
        __shared__ float t[32][33];
        int bid = blockIdx.y * 8 + blockIdx.x;     // 128 blocks
        int r0 = tid >> 5, cc = tid & 31;
        for (int tile = bid; tile < 320; tile += 128) {   // 16 kt x 20 vt
            int k0 = (tile / 20) * 32, v0 = (tile % 20) * 32;
            #pragma unroll
            for (int i = 0; i < 4; i++) {
                int r = r0 + i * 8;
                t[r][cc] = W_out[(size_t)(k0 + r) * Vc + v0 + cc];
            }
            __syncthreads();
            #pragma unroll
            for (int i = 0; i < 4; i++) {
                int r = r0 + i * 8;
                g_Wt[(size_t)(v0 + r) * Hc + k0 + cc] = __float2half_rn(t[cc][r]);
            }
            __syncthreads();
        }
        return;
    }

    const float* A; const float* W; const float* bias; float* C; int K;
    if (z == 0) {
        A = enc_out; W = W_enc; bias = b_enc; K = Ec;
        float* p; asm("cvta.global.u64 %0, g_enc;" : "=l"(p)); C = p;
    } else {
        if (blockIdx.y >= 8) return;
        A = dec_out; W = W_dec; bias = nullptr; K = Dc;
        float* p; asm("cvta.global.u64 %0, g_dec;" : "=l"(p)); C = p;
    }
    const int N = Hc;

    __shared__ float As[16][64];
    __shared__ float Ws[16][64];
    int row0 = blockIdx.y * 64, col0 = blockIdx.x * 64;
    int tx = tid & 15, ty = tid >> 4;
    float acc[4][4] = {};

    int rA = tid >> 2, kqA = (tid & 3) * 4;
    int kW = tid >> 4, cqW = (tid & 15) * 4;

    float4 areg = *(const float4*)&A[(size_t)(row0 + rA) * K + kqA];
    float4 wreg = *(const float4*)&W[(size_t)kW * N + col0 + cqW];

    const int NK = K / 16;
    for (int kt = 0; kt < NK; kt++) {
        __syncthreads();
        As[kqA + 0][rA] = areg.x;
        As[kqA + 1][rA] = areg.y;
        As[kqA + 2][rA] = areg.z;
        As[kqA + 3][rA] = areg.w;
        *(float4*)&Ws[kW][cqW] = wreg;
        __syncthreads();
        if (kt + 1 < NK) {
            int k0 = (kt + 1) * 16;
            areg = *(const float4*)&A[(size_t)(row0 + rA) * K + k0 + kqA];
            wreg = *(const float4*)&W[(size_t)(k0 + kW) * N + col0 + cqW];
        }
        #pragma unroll
        for (int kk = 0; kk < 16; kk++) {
            float a[4], b[4];
            #pragma unroll
            for (int i = 0; i < 4; i++) a[i] = As[kk][ty * 4 + i];
            #pragma unroll
            for (int j = 0; j < 4; j++) b[j] = Ws[kk][tx * 4 + j];
            #pragma unroll
            for (int i = 0; i < 4; i++)
                #pragma unroll
                for (int j = 0; j < 4; j++)
                    acc[i][j] += a[i] * b[j];
        }
    }
    #pragma unroll
    for (int i = 0; i < 4; i++) {
        int r = row0 + ty * 4 + i;
        #pragma unroll
        for (int j = 0; j < 4; j++) {
            int c = col0 + tx * 4 + j;
            float v = acc[i][j];
            if (bias) v += bias[c];
            C[(size_t)r * N + c] = v;
        }
    }
}

// ---------------------------------------------------------------------------
// Fused joint kernel v3: CTA = (bt, u-half). 2048 CTAs, 2 CTAs/SM.
//   A[64u x 512k] fp16(tanh.approx(enc+dec)) resident in SMEM (64KB),
//   filled JIT during v-tile 0, one 8KB chunk per iteration.
//   5 v-tiles of 128. W chunk [128v x 64k] = 16KB via 3-buf cp.async ring.
//   8 warps, warp tile 32x32 (2m x 4n), m16n8k16 fp16->fp32, bias-init acc.
// ---------------------------------------------------------------------------
#define ACHK 8192                   // A chunk: 64 rows x 64 halfs
#define WCH  16384                  // W chunk: 128 rows x 64 halfs
#define W_OFF (8 * ACHK)            // A = 64KB
#define JSMEM (W_OFF + 3 * WCH)     // 114688 B = 112KB
#define NIT 40

struct JCtx {
    uint32_t sb;
    const float* encR;
    const float* decB;   // dec rows for this u-half
};

// Fill A chunk k (64 rows x 64 k) — whole CTA, 512 vec8 units, 2/thread.
__device__ __forceinline__ void fillA(const JCtx& c, int k, int tid) {
    int K0 = k * 64;
    #pragma unroll
    for (int i = 0; i < 2; i++) {
        int idx = i * 256 + tid;           // 512 units of 8 halfs
        int r = idx >> 3, kg = idx & 7;
        int kc = K0 + kg * 8;
        float4 d0 = *(const float4*)(c.decB + (size_t)r * Hc + kc);
        float4 d1 = *(const float4*)(c.decB + (size_t)r * Hc + kc + 4);
        float4 e0 = *(const float4*)(c.encR + kc);
        float4 e1 = *(const float4*)(c.encR + kc + 4);
        uint4 q;
        q.x = pack2(tanh_fast(d0.x + e0.x), tanh_fast(d0.y + e0.y));
        q.y = pack2(tanh_fast(d0.z + e0.z), tanh_fast(d0.w + e0.w));
        q.z = pack2(tanh_fast(d1.x + e1.x), tanh_fast(d1.y + e1.y));
        q.w = pack2(tanh_fast(d1.z + e1.z), tanh_fast(d1.w + e1.w));
        uint32_t off = (uint32_t)k * ACHK + r * 128 + (((uint32_t)kg * 16) ^ ((r & 7) << 4));
        asm volatile("st.shared.v4.b32 [%0], {%1,%2,%3,%4};"
                     :: "r"(c.sb + off), "r"(q.x), "r"(q.y), "r"(q.z), "r"(q.w)
                     : "memory");
    }
}

// Load W chunk i (vt = i>>3, k = i&7): rows [vt*128, vt*128+128), 4/thread.
__device__ __forceinline__ void loadW(uint32_t sb, int i, int tid) {
    int vt = i >> 3, k = i & 7;
    uint32_t dstb = sb + W_OFF + (uint32_t)(i % 3) * WCH;
    const __half* src = g_Wt + ((size_t)vt * 128) * Hc + k * 64;
    #pragma unroll
    for (int j = 0; j < 4; j++) {
        int idx = j * 256 + tid;           // 1024 units
        int r = idx >> 3, kg = idx & 7;
        cp16(dstb + r * 128 + (((uint32_t)kg * 16) ^ ((r & 7) << 4)),
             src + (size_t)r * Hc + kg * 8);
    }
}

__global__ __launch_bounds__(256, 2) void joint_kernel(
    const float* __restrict__ bout, float* __restrict__ out)
{
    extern __shared__ char smem[];
    JCtx c;
    c.sb = smem_u32(smem);
    int tid = threadIdx.x, l = tid & 31, w = tid >> 5;
    int bx = blockIdx.x;
    int bt = bx >> 1, uh = bx & 1;
    int b = bt >> 8;
    c.encR = g_enc + (size_t)bt * Hc;
    c.decB = g_dec + ((size_t)b * Uc + uh * 64) * Hc;

    int m0 = (w >> 2) * 32;           // 0 / 32
    int n0 = (w & 3) * 32;            // 0 / 32 / 64 / 96
    int rowA = l & 15, khA = (l >> 4) * 16;
    int rowB = (l & 7) + ((l >> 4) << 3), khB = ((l >> 3) & 1) * 16;
    int gr = l >> 2, ct = l & 3;

    // Prologue: W chunks 0,1 in flight; A chunk 0 computed.
    loadW(c.sb, 0, tid); cp_commit();
    loadW(c.sb, 1, tid); cp_commit();
    fillA(c, 0, tid);

    float acc[2][4][4];
    float* outbt = out + ((size_t)bt * Uc + uh * 64) * Vc;

    for (int i = 0; i < NIT; i++) {
        int vt = i >> 3, k = i & 7;
        cp_wait1();
        __syncthreads();   // W chunk i visible; A chunk k visible (vt==0)

        if (k == 0) {   // init accumulators from bias
            #pragma unroll
            for (int nf = 0; nf < 4; nf++) {
                int cc = vt * 128 + n0 + nf * 8 + 2 * ct;
                float b0 = __ldg(&bout[cc]), b1 = __ldg(&bout[cc + 1]);
                #pragma unroll
                for (int mf = 0; mf < 2; mf++) {
                    acc[mf][nf][0] = b0; acc[mf][nf][1] = b1;
                    acc[mf][nf][2] = b0; acc[mf][nf][3] = b1;
                }
            }
        }

        uint32_t Ab = c.sb + (uint32_t)k * ACHK;
        uint32_t Wb = c.sb + W_OFF + (uint32_t)(i % 3) * WCH;
        #pragma unroll
        for (int ks = 0; ks < 4; ks++) {
            uint32_t a[2][4], bq[2][4];
            #pragma unroll
            for (int mf = 0; mf < 2; mf++) {
                int r = m0 + mf * 16 + rowA;
                ldmx4(a[mf], Ab + r * 128 + (((uint32_t)(ks * 32 + khA)) ^ ((r & 7) << 4)));
            }
            #pragma unroll
            for (int nb = 0; nb < 2; nb++) {
                int r = n0 + nb * 16 + rowB;
                ldmx4(bq[nb], Wb + r * 128 + (((uint32_t)(ks * 32 + khB)) ^ ((r & 7) << 4)));
            }
            #pragma unroll
            for (int mf = 0; mf < 2; mf++)
                #pragma unroll
                for (int nf = 0; nf < 4; nf++)
                    mma16816(acc[mf][nf], a[mf],
                             bq[nf >> 1][2 * (nf & 1)], bq[nf >> 1][2 * (nf & 1) + 1]);
        }

        if (vt == 0 && k < 7) fillA(c, k + 1, tid);   // hidden under MMA
        if (i + 2 < NIT) loadW(c.sb, i + 2, tid);
        cp_commit();   // uniform commit keeps wait_group bookkeeping simple

        if (k == 7) {   // epilogue for v-tile (bias already in acc)
            #pragma unroll
            for (int nf = 0; nf < 4; nf++) {
                int cc = vt * 128 + n0 + nf * 8 + 2 * ct;
                #pragma unroll
                for (int mf = 0; mf < 2; mf++) {
                    int u = m0 + mf * 16 + gr;
                    float* p = outbt + (size_t)u * Vc + cc;
                    float2 t0; t0.x = acc[mf][nf][0]; t0.y = acc[mf][nf][1];
                    float2 t1; t1.x = acc[mf][nf][2]; t1.y = acc[mf][nf][3];
                    *(float2*)p = t0;
                    *(float2*)(p + 8 * Vc) = t1;
                }
            }
        }
    }
}

// ---------------------------------------------------------------------------
extern "C" void kernel_launch(void* const* d_in, const int* in_sizes, int n_in,
                              void* d_out, int out_size)
{
    const float* enc_out = (const float*)d_in[0];
    const float* dec_out = (const float*)d_in[1];
    const float* W_enc   = (const float*)d_in[2];
    const float* b_enc   = (const float*)d_in[3];
    const float* W_dec   = (const float*)d_in[4];
    const float* W_out   = (const float*)d_in[5];
    const float* b_out   = (const float*)d_in[6];
    float* out = (float*)d_out;

    cudaFuncSetAttribute(joint_kernel,
                         cudaFuncAttributeMaxDynamicSharedMemorySize, JSMEM);

    prep_kernel<<<dim3(8, 16, 3), 256>>>(enc_out, dec_out, W_enc, b_enc, W_dec, W_out);
    joint_kernel<<<2 * Bc * Tc, 256, JSMEM>>>(b_out, out);
}